// round 12
// baseline (speedup 1.0000x reference)
#include <cuda_runtime.h>

// CapsNet dynamic routing, FFMA2 GEMMs.
// R12: gemm_Ya at 512 thr / 4x8 per-thread tile (32 warps/SM, 8 per SMSP) to
// cover the LDS->pack->FFMA2 dependency head that left it at 47% fma.
// x: [256, 2401, 8] fp32   W: [2401, 8, 16, 8] fp32   out: [256, 8, 16] fp32

#define IN_CAPS 2401
#define BATCH 256
#define KTOT 19208                 // 2401*8
#define NOC 128                    // 8*16
#define NSPLIT 73
#define CHUNK 264                  // 72*264 + 200 = 19208, multiples of 8

typedef unsigned long long ull;

__device__ float g_Spart[(size_t)NSPLIT * BATCH * NOC];  // 9.57 MB
__device__ float g_V[BATCH * NOC];
__device__ float g_b[IN_CAPS * 8];
__device__ float g_bp[2][IN_CAPS * 8];
__device__ float g_C[IN_CAPS * 8];

__device__ __forceinline__ void ffma2(ull& acc, ull a, ull b) {
    asm("fma.rn.f32x2 %0, %1, %2, %0;" : "+l"(acc) : "l"(a), "l"(b));
}
__device__ __forceinline__ ull pack2(float x) {
    ull r;
    unsigned u = __float_as_uint(x);
    asm("mov.b64 %0, {%1, %1};" : "=l"(r) : "r"(u));
    return r;
}

// ---------------------------------------------------------------------------
__global__ void init_kernel() {
    int t = blockIdx.x * blockDim.x + threadIdx.x;
    if (t < IN_CAPS * 8) { g_b[t] = 0.0f; g_C[t] = 0.125f; }
}

// b += a (both K-split partials), softmax over o -> C
__global__ void __launch_bounds__(128) compute_C_kernel() {
    int i = blockIdx.x * 128 + threadIdx.x;
    if (i >= IN_CAPS) return;
    float bv[8];
#pragma unroll
    for (int o = 0; o < 8; o++) {
        bv[o] = g_b[i * 8 + o] + g_bp[0][i * 8 + o] + g_bp[1][i * 8 + o];
        g_b[i * 8 + o] = bv[o];
    }
    float mx = -1e30f;
#pragma unroll
    for (int o = 0; o < 8; o++) mx = fmaxf(mx, bv[o]);
    float sum = 0.0f;
#pragma unroll
    for (int o = 0; o < 8; o++) { bv[o] = expf(bv[o] - mx); sum += bv[o]; }
    float inv = 1.0f / sum;
#pragma unroll
    for (int o = 0; o < 8; o++) g_C[i * 8 + o] = bv[o] * inv;
}

// ---------------------------------------------------------------------------
// S = X @ (C .* W), split-K partials. grid (2, 73) x 256 thr. (Unchanged —
// measured at/near the FFMA2 roofline.)
__global__ void __launch_bounds__(256, 2) gemm_S_kernel(const float* __restrict__ X,
                                                        const float* __restrict__ W) {
    __shared__ __align__(16) float Xs[8][132];
    __shared__ __align__(16) float Ms[8][132];

    int b0 = blockIdx.x * 128;
    int kstart = blockIdx.y * CHUNK;
    int kend = min(kstart + CHUNK, KTOT);
    int t = threadIdx.x;
    int tx = t & 15, ty = t >> 4;

    ull acc[8][4];
#pragma unroll
    for (int r = 0; r < 8; r++)
#pragma unroll
        for (int j = 0; j < 4; j++) acc[r][j] = 0ull;

    int xbb = t >> 1, xkp = (t & 1) * 4;
    int wl = t * 4;
    int wo = wl >> 7, wc = (wl >> 3) & 15, wd = wl & 7;
    int wcol = wo * 16 + wc;

    float4 xv = *reinterpret_cast<const float4*>(X + (size_t)(b0 + xbb) * KTOT + kstart + xkp);
    float4 wv = *reinterpret_cast<const float4*>(W + (size_t)(kstart >> 3) * 1024 + wl);
    float cc = g_C[(kstart >> 3) * 8 + wo];

    for (int k0 = kstart; k0 < kend; k0 += 8) {
        __syncthreads();
        Xs[xkp + 0][xbb] = xv.x; Xs[xkp + 1][xbb] = xv.y;
        Xs[xkp + 2][xbb] = xv.z; Xs[xkp + 3][xbb] = xv.w;
        Ms[wd + 0][wcol] = cc * wv.x; Ms[wd + 1][wcol] = cc * wv.y;
        Ms[wd + 2][wcol] = cc * wv.z; Ms[wd + 3][wcol] = cc * wv.w;
        __syncthreads();

        int kn = k0 + 8;
        if (kn < kend) {
            xv = *reinterpret_cast<const float4*>(X + (size_t)(b0 + xbb) * KTOT + kn + xkp);
            wv = *reinterpret_cast<const float4*>(W + (size_t)(kn >> 3) * 1024 + wl);
            cc = g_C[(kn >> 3) * 8 + wo];
        }

#pragma unroll
        for (int kk = 0; kk < 8; kk++) {
            ull mv[4];
#pragma unroll
            for (int jj = 0; jj < 4; jj++)
                mv[jj] = *reinterpret_cast<const ull*>(&Ms[kk][jj * 32 + tx * 2]);
            float4 xa = *reinterpret_cast<const float4*>(&Xs[kk][ty * 8]);
            float4 xb = *reinterpret_cast<const float4*>(&Xs[kk][ty * 8 + 4]);
            float xr[8] = {xa.x, xa.y, xa.z, xa.w, xb.x, xb.y, xb.z, xb.w};
#pragma unroll
            for (int rr = 0; rr < 8; rr++) {
                ull a = pack2(xr[rr]);
#pragma unroll
                for (int jj = 0; jj < 4; jj++) ffma2(acc[rr][jj], a, mv[jj]);
            }
        }
    }

    float* out = g_Spart + (size_t)blockIdx.y * (BATCH * NOC);
#pragma unroll
    for (int rr = 0; rr < 8; rr++) {
        int bb = b0 + ty * 8 + rr;
#pragma unroll
        for (int jj = 0; jj < 4; jj++)
            *reinterpret_cast<float2*>(out + (size_t)bb * NOC + jj * 32 + tx * 2) =
                *reinterpret_cast<float2*>(&acc[rr][jj]);
    }
}

// ---------------------------------------------------------------------------
// Sum 73 partials + squash. float4, 8 partial-lanes, grid 256 x 256 thr.
__global__ void __launch_bounds__(256) reduce_squash_kernel(float* __restrict__ out, int last) {
    int id = blockIdx.x * 256 + threadIdx.x;
    int gg = id >> 3;
    int q = id & 7;
    const float4* sp = reinterpret_cast<const float4*>(g_Spart);

    float4 s = make_float4(0.f, 0.f, 0.f, 0.f);
#pragma unroll 5
    for (int p = q; p < NSPLIT; p += 8) {
        float4 v = sp[(size_t)p * (BATCH * NOC / 4) + gg];
        s.x += v.x; s.y += v.y; s.z += v.z; s.w += v.w;
    }
#pragma unroll
    for (int off = 1; off <= 4; off <<= 1) {
        s.x += __shfl_xor_sync(0xffffffffu, s.x, off);
        s.y += __shfl_xor_sync(0xffffffffu, s.y, off);
        s.z += __shfl_xor_sync(0xffffffffu, s.z, off);
        s.w += __shfl_xor_sync(0xffffffffu, s.w, off);
    }
    float msq = s.x * s.x + s.y * s.y + s.z * s.z + s.w * s.w;
    msq += __shfl_xor_sync(0xffffffffu, msq, 8);
    msq += __shfl_xor_sync(0xffffffffu, msq, 16);
    float f = sqrtf(msq) / (1.0f + msq);
    float4 v = make_float4(s.x * f, s.y * f, s.z * f, s.w * f);
    if (q == 0) {
        reinterpret_cast<float4*>(g_V)[gg] = v;
        if (last) reinterpret_cast<float4*>(out)[gg] = v;
    }
}

// ---------------------------------------------------------------------------
// Y = X^T @ V, K-split 2, fused agreement -> g_bp[split].
// grid (151, 2) x 512 thr, 64 regs (occ 2 -> 32 warps/SM).
// CTA tile 128 K-rows x 128 cols; per-thread 4x8 (acc = 32 regs).
// Warp w owns capsule i = r0/8 + w; d-halves combined via shfl_xor 16.
__global__ void __launch_bounds__(512, 2) gemm_Ya_kernel(const float* __restrict__ X,
                                                         const float* __restrict__ W) {
    __shared__ __align__(16) float Xts[8][132];
    __shared__ __align__(16) float Vs[8][132];

    int r0 = blockIdx.x * 128;
    int split = blockIdx.y;
    int kbeg = split * 128;
    int t = threadIdx.x;
    int tx = t & 15, ty = t >> 4;      // ty 0..31: rows ty*4..ty*4+3

    ull acc[4][4];
#pragma unroll
    for (int r = 0; r < 4; r++)
#pragma unroll
        for (int j = 0; j < 4; j++) acc[r][j] = 0ull;

    // loaders: threads 0-255 load X, 256-511 load V (independent warps).
    int lk = (t & 255) >> 5;           // 0..7
    int lq = (t & 31) * 4;             // 0..124
    bool isx = t < 256;
    bool xok = (r0 + lq + 4) <= KTOT;

    float4 pv;
    if (isx) {
        pv = xok ? *reinterpret_cast<const float4*>(X + (size_t)(kbeg + lk) * KTOT + r0 + lq)
                 : make_float4(0.f, 0.f, 0.f, 0.f);
    } else {
        pv = *reinterpret_cast<const float4*>(g_V + (kbeg + lk) * NOC + lq);
    }

    for (int cs = 0; cs < 16; cs++) {
        __syncthreads();
        if (isx) *reinterpret_cast<float4*>(&Xts[lk][lq]) = pv;
        else     *reinterpret_cast<float4*>(&Vs[lk][lq]) = pv;
        __syncthreads();

        if (cs + 1 < 16) {
            int kk = kbeg + (cs + 1) * 8 + lk;
            if (isx) {
                pv = xok ? *reinterpret_cast<const float4*>(X + (size_t)kk * KTOT + r0 + lq)
                         : make_float4(0.f, 0.f, 0.f, 0.f);
            } else {
                pv = *reinterpret_cast<const float4*>(g_V + kk * NOC + lq);
            }
        }

#pragma unroll
        for (int kk2 = 0; kk2 < 8; kk2++) {
            ull mv[4];
#pragma unroll
            for (int jj = 0; jj < 4; jj++)
                mv[jj] = *reinterpret_cast<const ull*>(&Vs[kk2][jj * 32 + tx * 2]);
            float4 xa = *reinterpret_cast<const float4*>(&Xts[kk2][ty * 4]);
            float xr[4] = {xa.x, xa.y, xa.z, xa.w};
#pragma unroll
            for (int rr = 0; rr < 4; rr++) {
                ull a = pack2(xr[rr]);
#pragma unroll
                for (int jj = 0; jj < 4; jj++) ffma2(acc[rr][jj], a, mv[jj]);
            }
        }
    }

    // Agreement: warp w owns capsule i = r0/8 + w. Thread rows = 8w + dh*4 + rr
    // (dh = ty&1), cols jj*32 + tx*2 -> o = jj*2 + (tx>>3), c = (tx&7)*2.
    int w = t >> 5;
    int lane = t & 31;
    int i = r0 / 8 + w;
    int iw = min(i, IN_CAPS - 1);
    int dh = ty & 1;
    int ohi = tx >> 3;
    int c = (tx & 7) * 2;
    float s[4];
#pragma unroll
    for (int jj = 0; jj < 4; jj++) {
        int oo = jj * 2 + ohi;
        const float4* wp =
            reinterpret_cast<const float4*>(W + (size_t)iw * 1024 + oo * 128 + c * 8 + dh * 4);
        float4 w0 = wp[0];   // W[i, oo, c,   dh*4 .. +3]
        float4 w1 = wp[2];   // W[i, oo, c+1, dh*4 .. +3]
        float wv0[4] = {w0.x, w0.y, w0.z, w0.w};
        float wv1[4] = {w1.x, w1.y, w1.z, w1.w};
        float sum = 0.0f;
#pragma unroll
        for (int rr = 0; rr < 4; rr++) {
            float2 y = *reinterpret_cast<float2*>(&acc[rr][jj]);
            sum += wv0[rr] * y.x + wv1[rr] * y.y;
        }
        s[jj] = sum;
    }
#pragma unroll
    for (int jj = 0; jj < 4; jj++) {
        s[jj] += __shfl_xor_sync(0xffffffffu, s[jj], 1);
        s[jj] += __shfl_xor_sync(0xffffffffu, s[jj], 2);
        s[jj] += __shfl_xor_sync(0xffffffffu, s[jj], 4);
        s[jj] += __shfl_xor_sync(0xffffffffu, s[jj], 16);
    }
    if ((lane & 0x17) == 0 && i < IN_CAPS) {   // lanes 0 and 8
#pragma unroll
        for (int jj = 0; jj < 4; jj++)
            g_bp[split][i * 8 + jj * 2 + ohi] = s[jj] * (1.0f / 256.0f);
    }
}

// ---------------------------------------------------------------------------
extern "C" void kernel_launch(void* const* d_in, const int* in_sizes, int n_in,
                              void* d_out, int out_size) {
    const float* x;
    const float* W;
    if (in_sizes[0] == BATCH * KTOT) {
        x = (const float*)d_in[0];
        W = (const float*)d_in[1];
    } else {
        x = (const float*)d_in[1];
        W = (const float*)d_in[0];
    }
    float* out = (float*)d_out;

    init_kernel<<<76, 256>>>();

    for (int it = 0; it < 3; it++) {
        gemm_S_kernel<<<dim3(2, NSPLIT), 256>>>(x, W);
        reduce_squash_kernel<<<256, 256>>>(out, it == 2 ? 1 : 0);
        if (it < 2) {
            gemm_Ya_kernel<<<dim3(151, 2), 512>>>(x, W);
            compute_C_kernel<<<19, 128>>>();
        }
    }
}

// round 13
// speedup vs baseline: 1.0455x; 1.0455x over previous
#include <cuda_runtime.h>

// CapsNet dynamic routing, FFMA2 GEMMs.
// R13: reduce_squash re-mapped for coalescing (column index on fast lane bits:
// warp = 8 contiguous float4-cols x 4 partial lanes -> 4x128B transactions
// instead of 32 scattered sectors). gemm_S and gemm_Ya = best measured configs.
// x: [256, 2401, 8] fp32   W: [2401, 8, 16, 8] fp32   out: [256, 8, 16] fp32

#define IN_CAPS 2401
#define BATCH 256
#define KTOT 19208                 // 2401*8
#define NOC 128                    // 8*16
#define NSPLIT 73
#define CHUNK 264                  // 72*264 + 200 = 19208, multiples of 8

typedef unsigned long long ull;

__device__ float g_Spart[(size_t)NSPLIT * BATCH * NOC];  // 9.57 MB
__device__ float g_V[BATCH * NOC];
__device__ float g_b[IN_CAPS * 8];
__device__ float g_bp[2][IN_CAPS * 8];
__device__ float g_C[IN_CAPS * 8];

__device__ __forceinline__ void ffma2(ull& acc, ull a, ull b) {
    asm("fma.rn.f32x2 %0, %1, %2, %0;" : "+l"(acc) : "l"(a), "l"(b));
}
__device__ __forceinline__ ull pack2(float x) {
    ull r;
    unsigned u = __float_as_uint(x);
    asm("mov.b64 %0, {%1, %1};" : "=l"(r) : "r"(u));
    return r;
}

// ---------------------------------------------------------------------------
__global__ void init_kernel() {
    int t = blockIdx.x * blockDim.x + threadIdx.x;
    if (t < IN_CAPS * 8) { g_b[t] = 0.0f; g_C[t] = 0.125f; }
}

// b += a (both K-split partials), softmax over o -> C
__global__ void __launch_bounds__(128) compute_C_kernel() {
    int i = blockIdx.x * 128 + threadIdx.x;
    if (i >= IN_CAPS) return;
    float bv[8];
#pragma unroll
    for (int o = 0; o < 8; o++) {
        bv[o] = g_b[i * 8 + o] + g_bp[0][i * 8 + o] + g_bp[1][i * 8 + o];
        g_b[i * 8 + o] = bv[o];
    }
    float mx = -1e30f;
#pragma unroll
    for (int o = 0; o < 8; o++) mx = fmaxf(mx, bv[o]);
    float sum = 0.0f;
#pragma unroll
    for (int o = 0; o < 8; o++) { bv[o] = expf(bv[o] - mx); sum += bv[o]; }
    float inv = 1.0f / sum;
#pragma unroll
    for (int o = 0; o < 8; o++) g_C[i * 8 + o] = bv[o] * inv;
}

// ---------------------------------------------------------------------------
// S = X @ (C .* W), split-K partials. grid (2, 73) x 256 thr. (At the FFMA2
// roofline — unchanged.)
__global__ void __launch_bounds__(256, 2) gemm_S_kernel(const float* __restrict__ X,
                                                        const float* __restrict__ W) {
    __shared__ __align__(16) float Xs[8][132];
    __shared__ __align__(16) float Ms[8][132];

    int b0 = blockIdx.x * 128;
    int kstart = blockIdx.y * CHUNK;
    int kend = min(kstart + CHUNK, KTOT);
    int t = threadIdx.x;
    int tx = t & 15, ty = t >> 4;

    ull acc[8][4];
#pragma unroll
    for (int r = 0; r < 8; r++)
#pragma unroll
        for (int j = 0; j < 4; j++) acc[r][j] = 0ull;

    int xbb = t >> 1, xkp = (t & 1) * 4;
    int wl = t * 4;
    int wo = wl >> 7, wc = (wl >> 3) & 15, wd = wl & 7;
    int wcol = wo * 16 + wc;

    float4 xv = *reinterpret_cast<const float4*>(X + (size_t)(b0 + xbb) * KTOT + kstart + xkp);
    float4 wv = *reinterpret_cast<const float4*>(W + (size_t)(kstart >> 3) * 1024 + wl);
    float cc = g_C[(kstart >> 3) * 8 + wo];

    for (int k0 = kstart; k0 < kend; k0 += 8) {
        __syncthreads();
        Xs[xkp + 0][xbb] = xv.x; Xs[xkp + 1][xbb] = xv.y;
        Xs[xkp + 2][xbb] = xv.z; Xs[xkp + 3][xbb] = xv.w;
        Ms[wd + 0][wcol] = cc * wv.x; Ms[wd + 1][wcol] = cc * wv.y;
        Ms[wd + 2][wcol] = cc * wv.z; Ms[wd + 3][wcol] = cc * wv.w;
        __syncthreads();

        int kn = k0 + 8;
        if (kn < kend) {
            xv = *reinterpret_cast<const float4*>(X + (size_t)(b0 + xbb) * KTOT + kn + xkp);
            wv = *reinterpret_cast<const float4*>(W + (size_t)(kn >> 3) * 1024 + wl);
            cc = g_C[(kn >> 3) * 8 + wo];
        }

#pragma unroll
        for (int kk = 0; kk < 8; kk++) {
            ull mv[4];
#pragma unroll
            for (int jj = 0; jj < 4; jj++)
                mv[jj] = *reinterpret_cast<const ull*>(&Ms[kk][jj * 32 + tx * 2]);
            float4 xa = *reinterpret_cast<const float4*>(&Xs[kk][ty * 8]);
            float4 xb = *reinterpret_cast<const float4*>(&Xs[kk][ty * 8 + 4]);
            float xr[8] = {xa.x, xa.y, xa.z, xa.w, xb.x, xb.y, xb.z, xb.w};
#pragma unroll
            for (int rr = 0; rr < 8; rr++) {
                ull a = pack2(xr[rr]);
#pragma unroll
                for (int jj = 0; jj < 4; jj++) ffma2(acc[rr][jj], a, mv[jj]);
            }
        }
    }

    float* out = g_Spart + (size_t)blockIdx.y * (BATCH * NOC);
#pragma unroll
    for (int rr = 0; rr < 8; rr++) {
        int bb = b0 + ty * 8 + rr;
#pragma unroll
        for (int jj = 0; jj < 4; jj++)
            *reinterpret_cast<float2*>(out + (size_t)bb * NOC + jj * 32 + tx * 2) =
                *reinterpret_cast<float2*>(&acc[rr][jj]);
    }
}

// ---------------------------------------------------------------------------
// Sum 73 partials + squash. COALESCED mapping: gg = id>>2 (contiguous columns
// across lanes), q = id&3 (partial lane). grid 128 x 256 thr (32768 threads).
__global__ void __launch_bounds__(256) reduce_squash_kernel(float* __restrict__ out, int last) {
    int id = blockIdx.x * 256 + threadIdx.x;
    int gg = id >> 2;        // float4 column 0..8191
    int q = id & 3;          // partial lane
    const float4* sp = reinterpret_cast<const float4*>(g_Spart);

    float4 s = make_float4(0.f, 0.f, 0.f, 0.f);
#pragma unroll 8
    for (int p = q; p < NSPLIT; p += 4) {
        float4 v = sp[(size_t)p * (BATCH * NOC / 4) + gg];
        s.x += v.x; s.y += v.y; s.z += v.z; s.w += v.w;
    }
    // combine the 4 partial lanes (lane bits 0-1)
#pragma unroll
    for (int off = 1; off <= 2; off <<= 1) {
        s.x += __shfl_xor_sync(0xffffffffu, s.x, off);
        s.y += __shfl_xor_sync(0xffffffffu, s.y, off);
        s.z += __shfl_xor_sync(0xffffffffu, s.z, off);
        s.w += __shfl_xor_sync(0xffffffffu, s.w, off);
    }
    // squash group = 4 float4 columns (gg bits 0-1 = lane bits 2-3)
    float msq = s.x * s.x + s.y * s.y + s.z * s.z + s.w * s.w;
    msq += __shfl_xor_sync(0xffffffffu, msq, 4);
    msq += __shfl_xor_sync(0xffffffffu, msq, 8);
    float f = sqrtf(msq) / (1.0f + msq);
    float4 v = make_float4(s.x * f, s.y * f, s.z * f, s.w * f);
    if (q == 0) {
        reinterpret_cast<float4*>(g_V)[gg] = v;
        if (last) reinterpret_cast<float4*>(out)[gg] = v;
    }
}

// ---------------------------------------------------------------------------
// Y = X^T @ V, K-split 2 over batch, fused agreement into g_bp[split].
// grid (301, 2) x 128 thr, occ 4 (best measured Ya config: 31.7 us).
// CTA tile 64 K-rows x 128 cols; per-thread 8x8. ty owns capsule r0/8+ty.
__global__ void __launch_bounds__(128, 4) gemm_Ya_kernel(const float* __restrict__ X,
                                                         const float* __restrict__ W) {
    __shared__ float Xts[8][68];
    __shared__ float Vs[8][132];

    int r0 = blockIdx.x * 64;
    int split = blockIdx.y;
    int kbeg = split * 128, kfin = kbeg + 128;
    int t = threadIdx.x;
    int tx = t & 15, ty = t >> 4;

    ull acc[8][4];
#pragma unroll
    for (int r = 0; r < 8; r++)
#pragma unroll
        for (int j = 0; j < 4; j++) acc[r][j] = 0ull;

    int lkk = t >> 4;            // 0..7
    int lq = (t & 15) * 4;       // 0..60
    bool xok = (r0 + lq) < KTOT;

    float4 xv = xok ? *reinterpret_cast<const float4*>(X + (size_t)(kbeg + lkk) * KTOT + r0 + lq)
                    : make_float4(0.f, 0.f, 0.f, 0.f);
    float4 va = *reinterpret_cast<const float4*>(g_V + (kbeg + lkk) * NOC + lq);
    float4 vb = *reinterpret_cast<const float4*>(g_V + (kbeg + lkk) * NOC + lq + 64);

    for (int k0 = kbeg; k0 < kfin; k0 += 8) {
        __syncthreads();
        *reinterpret_cast<float4*>(&Xts[lkk][lq]) = xv;
        *reinterpret_cast<float4*>(&Vs[lkk][lq]) = va;
        *reinterpret_cast<float4*>(&Vs[lkk][lq + 64]) = vb;
        __syncthreads();

        int kn = k0 + 8;
        if (kn < kfin) {
            xv = xok ? *reinterpret_cast<const float4*>(X + (size_t)(kn + lkk) * KTOT + r0 + lq)
                     : make_float4(0.f, 0.f, 0.f, 0.f);
            va = *reinterpret_cast<const float4*>(g_V + (kn + lkk) * NOC + lq);
            vb = *reinterpret_cast<const float4*>(g_V + (kn + lkk) * NOC + lq + 64);
        }

#pragma unroll
        for (int kk = 0; kk < 8; kk++) {
            ull mv[4];
#pragma unroll
            for (int jj = 0; jj < 4; jj++)
                mv[jj] = *reinterpret_cast<const ull*>(&Vs[kk][jj * 32 + tx * 2]);
            float4 xa = *reinterpret_cast<const float4*>(&Xts[kk][ty * 8]);
            float4 xb = *reinterpret_cast<const float4*>(&Xts[kk][ty * 8 + 4]);
            float xr[8] = {xa.x, xa.y, xa.z, xa.w, xb.x, xb.y, xb.z, xb.w};
#pragma unroll
            for (int rr = 0; rr < 8; rr++) {
                ull a = pack2(xr[rr]);
#pragma unroll
                for (int jj = 0; jj < 4; jj++) ffma2(acc[rr][jj], a, mv[jj]);
            }
        }
    }

    // Agreement partial: a[i,o] = (1/B) sum_{c,d,k in half} W * Y
    int i = r0 / 8 + ty;
    int iw = min(i, IN_CAPS - 1);
    int ohi = tx >> 3;
    int c = (tx & 7) * 2;
    float s[4];
#pragma unroll
    for (int jj = 0; jj < 4; jj++) {
        int oo = jj * 2 + ohi;
        const float4* wp = reinterpret_cast<const float4*>(W + (size_t)iw * 1024 + oo * 128 + c * 8);
        float4 w0 = wp[0], w1 = wp[1], w2 = wp[2], w3 = wp[3];
        float wlo[8] = {w0.x, w0.y, w0.z, w0.w, w1.x, w1.y, w1.z, w1.w};
        float whi[8] = {w2.x, w2.y, w2.z, w2.w, w3.x, w3.y, w3.z, w3.w};
        float sum = 0.0f;
#pragma unroll
        for (int d = 0; d < 8; d++) {
            float2 y = *reinterpret_cast<float2*>(&acc[d][jj]);
            sum += wlo[d] * y.x + whi[d] * y.y;
        }
        s[jj] = sum;
    }
#pragma unroll
    for (int jj = 0; jj < 4; jj++) {
        s[jj] += __shfl_xor_sync(0xffffffffu, s[jj], 1);
        s[jj] += __shfl_xor_sync(0xffffffffu, s[jj], 2);
        s[jj] += __shfl_xor_sync(0xffffffffu, s[jj], 4);
    }
    if ((tx & 7) == 0 && i < IN_CAPS) {
#pragma unroll
        for (int jj = 0; jj < 4; jj++)
            g_bp[split][i * 8 + jj * 2 + ohi] = s[jj] * (1.0f / 256.0f);
    }
}

// ---------------------------------------------------------------------------
extern "C" void kernel_launch(void* const* d_in, const int* in_sizes, int n_in,
                              void* d_out, int out_size) {
    const float* x;
    const float* W;
    if (in_sizes[0] == BATCH * KTOT) {
        x = (const float*)d_in[0];
        W = (const float*)d_in[1];
    } else {
        x = (const float*)d_in[1];
        W = (const float*)d_in[0];
    }
    float* out = (float*)d_out;

    init_kernel<<<76, 256>>>();

    for (int it = 0; it < 3; it++) {
        gemm_S_kernel<<<dim3(2, NSPLIT), 256>>>(x, W);
        reduce_squash_kernel<<<128, 256>>>(out, it == 2 ? 1 : 0);
        if (it < 2) {
            gemm_Ya_kernel<<<dim3(301, 2), 128>>>(x, W);
            compute_C_kernel<<<19, 128>>>();
        }
    }
}